// round 16
// baseline (speedup 1.0000x reference)
#include <cuda_runtime.h>
#include <cuda_fp16.h>
#include <math.h>
#include <stdint.h>

#define NB   2
#define SEQ  2048
#define EMB  1024
#define NH   16
#define NKV  8
#define HD   64
#define MROWS (NB*SEQ)   // 4096

// ---------------- scratch (no allocations allowed) ----------------
__device__ __half g_q [(size_t)MROWS * NH * HD];   // QSC-scaled fp16
__device__ __half g_k [(size_t)MROWS * NKV * HD];  // fp16
__device__ __half g_vt[(size_t)MROWS * NKV * HD];  // fp16 transposed [nb][kvh][d][s]
__device__ __half g_attn[(size_t)MROWS * NH * HD];
__device__ __half g_xt[(size_t)MROWS * EMB];
__device__ __half g_wq[(size_t)NH * HD * EMB];
__device__ __half g_wk[(size_t)NKV * HD * EMB];
__device__ __half g_wv[(size_t)NKV * HD * EMB];
__device__ __half g_wo[(size_t)EMB * NH * HD];

#define QSC 0.18033688011112042f   // 0.125 * log2(e)

// =====================================================================
// helpers
// =====================================================================
__device__ __forceinline__ uint32_t f2h2(float lo, float hi) {
    uint32_t r;
    asm("cvt.rn.f16x2.f32 %0, %1, %2;" : "=r"(r) : "f"(hi), "f"(lo));
    return r;
}
__device__ __forceinline__ void mma_f16(float* d, const uint32_t* a, const uint32_t* b) {
    asm volatile(
        "mma.sync.aligned.m16n8k16.row.col.f32.f16.f16.f32 "
        "{%0,%1,%2,%3}, {%4,%5,%6,%7}, {%8,%9}, {%0,%1,%2,%3};"
        : "+f"(d[0]), "+f"(d[1]), "+f"(d[2]), "+f"(d[3])
        : "r"(a[0]), "r"(a[1]), "r"(a[2]), "r"(a[3]), "r"(b[0]), "r"(b[1]));
}
__device__ __forceinline__ void ldsm_x4(uint32_t* r, uint32_t addr) {
    asm volatile("ldmatrix.sync.aligned.m8n8.x4.shared.b16 {%0,%1,%2,%3}, [%4];"
        : "=r"(r[0]), "=r"(r[1]), "=r"(r[2]), "=r"(r[3]) : "r"(addr));
}
__device__ __forceinline__ uint32_t smem_u32(const void* p) {
    uint32_t a;
    asm("{ .reg .u64 t; cvta.to.shared.u64 t, %1; cvt.u32.u64 %0, t; }" : "=r"(a) : "l"(p));
    return a;
}
#define CPCA16(dst, src) \
    asm volatile("cp.async.ca.shared.global [%0], [%1], 16;" :: "r"(dst), "l"(src))
#define CP_COMMIT() asm volatile("cp.async.commit_group;" ::: "memory")
#define CP_WAIT(n)  asm volatile("cp.async.wait_group %0;" :: "n"(n) : "memory")

// =====================================================================
// pre-round: x + weights -> fp16 scratch
// =====================================================================
#define X4  (MROWS * EMB / 4)
#define WQ4 (NH * HD * EMB / 4)
#define WK4 (NKV * HD * EMB / 4)
#define TOT4 (X4 + WQ4 + 2 * WK4 + WQ4)

__global__ __launch_bounds__(256)
void preround(const float* __restrict__ x,
              const float* __restrict__ wq, const float* __restrict__ wk,
              const float* __restrict__ wv, const float* __restrict__ wo)
{
    long i = (long)blockIdx.x * 256 + threadIdx.x;
    const float* src; __half* dst; long base;
    if (i < X4)                       { src = x;  dst = g_xt; base = 0; }
    else if (i < X4 + WQ4)            { src = wq; dst = g_wq; base = X4; }
    else if (i < X4 + WQ4 + WK4)      { src = wk; dst = g_wk; base = X4 + WQ4; }
    else if (i < X4 + WQ4 + 2 * WK4)  { src = wv; dst = g_wv; base = X4 + WQ4 + WK4; }
    else                              { src = wo; dst = g_wo; base = X4 + WQ4 + 2 * WK4; }
    long j = (i - base) * 4;
    float4 a = *(const float4*)(src + j);
    uint2 t = { f2h2(a.x, a.y), f2h2(a.z, a.w) };
    *(uint2*)(dst + j) = t;
}

// =====================================================================
// fp16 GEMM (ldmatrix fragments): 256 thr, 8 warps (2x4), warp 64x64,
// CTA 128x256, K-chunk 64 halves, cp.async.ca double-buffered.
// =====================================================================
#define LT 36
#define ABUF (128 * LT)
#define BBUF (256 * LT)
#define TBUF (ABUF + BBUF)
#define GSMEM_DYN (2 * TBUF * 4)

__device__ __forceinline__
void gemm_stage(uint32_t sbase, int buf, const __half* __restrict__ A,
                const __half* __restrict__ B, int K, int m0, int n0, int k0, int tid)
{
    uint32_t dA = sbase + (buf * TBUF) * 4;
    uint32_t dB = dA + ABUF * 4;
#pragma unroll
    for (int p = 0; p < 4; p++) {
        int c = tid + p * 256;
        int row = c >> 3;
        int ch  = c & 7;
        CPCA16(dA + (row * LT + ch * 4) * 4, A + (size_t)(m0 + row) * K + k0 + ch * 8);
    }
#pragma unroll
    for (int p = 0; p < 8; p++) {
        int c = tid + p * 256;
        int row = c >> 3;
        int ch  = c & 7;
        CPCA16(dB + (row * LT + ch * 4) * 4, B + (size_t)(n0 + row) * K + k0 + ch * 8);
    }
    CP_COMMIT();
}

__device__ __forceinline__
void gemm_body(const __half* __restrict__ A, const __half* __restrict__ B,
               const float* __restrict__ bias, void* __restrict__ Cout,
               int N, int K, int m0, int n0, int mode)
{
    extern __shared__ uint32_t gsm[];
    const uint32_t sbase = smem_u32(gsm);

    const int tid  = threadIdx.x;
    const int lane = tid & 31;
    const int wid  = tid >> 5;
    const int wm   = wid >> 2;
    const int wn   = wid & 3;
    const int fr   = lane >> 2;
    const int fc   = lane & 3;

    const int rowA = (lane & 7) + ((lane >> 3) & 1) * 8;
    const int offA = (lane >> 4) * 4;
    const int rowB = (lane & 7) + (lane >> 4) * 8;
    const int offB = ((lane >> 3) & 1) * 4;

    float acc[4][8][4];
#pragma unroll
    for (int mt = 0; mt < 4; mt++)
#pragma unroll
        for (int nt = 0; nt < 8; nt++)
#pragma unroll
            for (int i = 0; i < 4; i++) acc[mt][nt][i] = 0.f;

    gemm_stage(sbase, 0, A, B, K, m0, n0, 0, tid);

    const int NC = K / 64;
    for (int ch = 0; ch < NC; ch++) {
        if (ch + 1 < NC) {
            gemm_stage(sbase, (ch + 1) & 1, A, B, K, m0, n0, (ch + 1) * 64, tid);
            CP_WAIT(1);
        } else {
            CP_WAIT(0);
        }
        __syncthreads();

        const uint32_t asu = sbase + ((ch & 1) * TBUF) * 4;
        const uint32_t bsu = asu + ABUF * 4;

#pragma unroll
        for (int ks = 0; ks < 4; ks++) {
            uint32_t af[4][4], bf[8][2];
#pragma unroll
            for (int mt = 0; mt < 4; mt++)
                ldsm_x4(af[mt], asu + (((wm * 64 + mt * 16 + rowA) * LT) + ks * 8 + offA) * 4);
#pragma unroll
            for (int ntp = 0; ntp < 4; ntp++) {
                uint32_t m[4];
                ldsm_x4(m, bsu + (((wn * 64 + ntp * 16 + rowB) * LT) + ks * 8 + offB) * 4);
                bf[ntp * 2][0] = m[0]; bf[ntp * 2][1] = m[1];
                bf[ntp * 2 + 1][0] = m[2]; bf[ntp * 2 + 1][1] = m[3];
            }
#pragma unroll
            for (int mt = 0; mt < 4; mt++)
#pragma unroll
                for (int nt = 0; nt < 8; nt++)
                    mma_f16(acc[mt][nt], af[mt], bf[nt]);
        }
        __syncthreads();
    }

    const int c2 = fc * 2;
#pragma unroll
    for (int mt = 0; mt < 4; mt++) {
        int m = m0 + wm * 64 + mt * 16 + fr;
#pragma unroll
        for (int nt = 0; nt < 8; nt++) {
            int n = n0 + wn * 64 + nt * 8 + c2;
            if (mode == 0) {
                float* C = (float*)Cout;
                float b0 = bias ? bias[n] : 0.f, b1 = bias ? bias[n + 1] : 0.f;
                float2 v0 = { acc[mt][nt][0] + b0, acc[mt][nt][1] + b1 };
                float2 v1 = { acc[mt][nt][2] + b0, acc[mt][nt][3] + b1 };
                *(float2*)(C + (size_t)m * N + n)       = v0;
                *(float2*)(C + (size_t)(m + 8) * N + n) = v1;
            } else if (mode == 3) {
                int kvh = n >> 6, d = n & 63;
                int nb = m >> 11, s = m & (SEQ - 1);
                size_t rb = ((size_t)(nb * NKV + kvh) * HD + d) * SEQ;
                g_vt[rb + s]           = __float2half(acc[mt][nt][0]);
                g_vt[rb + SEQ + s]     = __float2half(acc[mt][nt][1]);
                g_vt[rb + s + 8]       = __float2half(acc[mt][nt][2]);
                g_vt[rb + SEQ + s + 8] = __float2half(acc[mt][nt][3]);
            } else {
                __half* C = (__half*)Cout;
                float sc = (mode == 2) ? QSC : 1.f;
                *(uint32_t*)(C + (size_t)m * N + n) =
                    f2h2(acc[mt][nt][0] * sc, acc[mt][nt][1] * sc);
                *(uint32_t*)(C + (size_t)(m + 8) * N + n) =
                    f2h2(acc[mt][nt][2] * sc, acc[mt][nt][3] * sc);
            }
        }
    }
}

__global__ __launch_bounds__(256)
void gemm_qkv()
{
    const int bx = blockIdx.x;
    const int m0 = blockIdx.y * 128;
    if (bx < 4)      gemm_body(g_xt, g_wq, nullptr, g_q, NH * HD,  EMB, m0, bx * 256, 2);
    else if (bx < 6) gemm_body(g_xt, g_wk, nullptr, g_k, NKV * HD, EMB, m0, (bx - 4) * 256, 1);
    else             gemm_body(g_xt, g_wv, nullptr, nullptr, NKV * HD, EMB, m0, (bx - 6) * 256, 3);
}

__global__ __launch_bounds__(256)
void gemm_out(const float* __restrict__ bias, float* __restrict__ C)
{
    gemm_body(g_attn, g_wo, bias, C, EMB, EMB, blockIdx.y * 128, blockIdx.x * 256, 0);
}

// =====================================================================
// Flash attention v10: GQA head-pairing. One CTA = (q-block, kvh, n),
// processes heads h0=2*kvh and h1=h0+1 sharing the same K/V tile.
// 8 warps x 16 q-rows (BQ=128), 256 threads, fp16 mma + ldmatrix.
// Each K/V fragment load feeds TWO mma (one per head).
// l accumulated via ones-column mma.
// Ks: [128][36]  Vt: [64][68]  Ps0/Ps1: [128][36] (Q then P, per head)
// =====================================================================
#define LTK 36
#define LTV 68
#define LTT 36

__global__ __launch_bounds__(256)
void flash_mma()
{
    extern __shared__ uint32_t smf[];
    uint32_t* Ks  = smf;                    // [128][36]
    uint32_t* Vt  = Ks + 128 * LTK;         // [64][68]
    uint32_t* Ps0 = Vt + 64 * LTV;          // [128][36]
    uint32_t* Ps1 = Ps0 + 128 * LTT;        // [128][36]
    const uint32_t ksu  = smem_u32(Ks);
    const uint32_t vtu  = smem_u32(Vt);
    const uint32_t ps0u = smem_u32(Ps0);
    const uint32_t ps1u = smem_u32(Ps1);

    const int tid  = threadIdx.x;
    const int lane = tid & 31;
    const int wid  = tid >> 5;              // 0..7 : q-rows [wid*16, wid*16+16)
    const int fr   = lane >> 2;
    const int fc   = lane & 3;

    const int rowA = (lane & 7) + ((lane >> 3) & 1) * 8;
    const int offA = (lane >> 4) * 4;
    const int rowB = (lane & 7) + (lane >> 4) * 8;
    const int offB = ((lane >> 3) & 1) * 4;

    const int q0  = blockIdx.x * 128;
    const int kvh = blockIdx.y;
    const int n   = blockIdx.z;
    const int h0  = kvh * 2;
    const float slope0 = exp2f(-(float)(h0 + 1)) * QSC;
    const float slope1 = slope0 * 0.5f;

    const uint32_t onesb[2] = { 0x3C003C00u, 0x3C003C00u };

    // ---- stage Q for both heads ----
#pragma unroll
    for (int p = 0; p < 4; p++) {
        int u = tid + p * 256;
        int qi = u >> 3;
        int c  = u & 7;
        const __half* qb = g_q + (size_t)(n * SEQ + q0 + qi) * (NH * HD) + h0 * HD;
        *(uint4*)&Ps0[qi * LTT + c * 4] = *(const uint4*)(qb + c * 8);
        *(uint4*)&Ps1[qi * LTT + c * 4] = *(const uint4*)(qb + HD + c * 8);
    }
    __syncthreads();

    const int r0 = wid * 16 + fr;
    uint32_t qf0[4][4], qf1[4][4];
#pragma unroll
    for (int ks = 0; ks < 4; ks++) {
        ldsm_x4(qf0[ks], ps0u + (((wid * 16 + rowA) * LTT) + ks * 8 + offA) * 4);
        ldsm_x4(qf1[ks], ps1u + (((wid * 16 + rowA) * LTT) + ks * 8 + offA) * 4);
    }

    float o0[8][4], o1[8][4], la0[4], la1[4];
#pragma unroll
    for (int nt = 0; nt < 8; nt++)
#pragma unroll
        for (int i = 0; i < 4; i++) { o0[nt][i] = 0.f; o1[nt][i] = 0.f; }
#pragma unroll
    for (int i = 0; i < 4; i++) { la0[i] = 0.f; la1[i] = 0.f; }
    float m00 = -INFINITY, m01 = -INFINITY;   // head0: rows fr, fr+8
    float m10 = -INFINITY, m11 = -INFINITY;   // head1

    const float gq0 = (float)(q0 + wid * 16 + fr);
    const float gq1 = gq0 + 8.f;

    for (int kb = 0; kb < SEQ / 128; kb++) {
        __syncthreads();

        // ---- stage K [128][64h] and Vt [64][128h] once for both heads ----
#pragma unroll
        for (int p = 0; p < 4; p++) {
            int u = tid + p * 256;
            int ki = u >> 3;
            int c  = u & 7;
            uint4 t = *(const uint4*)(g_k + (size_t)(n * SEQ + kb * 128 + ki) * (NKV * HD)
                                          + kvh * HD + c * 8);
            *(uint4*)&Ks[ki * LTK + c * 4] = t;
        }
#pragma unroll
        for (int p = 0; p < 4; p++) {
            int u = tid + p * 256;
            int d = u >> 4;
            int c = u & 15;
            uint4 t = *(const uint4*)(g_vt + ((size_t)(n * NKV + kvh) * HD + d) * SEQ
                                           + kb * 128 + c * 8);
            *(uint4*)&Vt[d * LTV + c * 4] = t;
        }
        __syncthreads();

#pragma unroll
        for (int kk = 0; kk < 2; kk++) {
            float s0[8][4], s1[8][4];
#pragma unroll
            for (int nt = 0; nt < 8; nt++)
#pragma unroll
                for (int i = 0; i < 4; i++) { s0[nt][i] = 0.f; s1[nt][i] = 0.f; }

            // ---- S = Q @ K^T, K fragments shared by both heads ----
#pragma unroll
            for (int ks = 0; ks < 4; ks++) {
                uint32_t bf[8][2];
#pragma unroll
                for (int ntp = 0; ntp < 4; ntp++) {
                    uint32_t m[4];
                    ldsm_x4(m, ksu + (((kk * 64 + ntp * 16 + rowB) * LTK) + ks * 8 + offB) * 4);
                    bf[ntp * 2][0] = m[0]; bf[ntp * 2][1] = m[1];
                    bf[ntp * 2 + 1][0] = m[2]; bf[ntp * 2 + 1][1] = m[3];
                }
#pragma unroll
                for (int nt = 0; nt < 8; nt++) {
                    mma_f16(s0[nt], qf0[ks], bf[nt]);
                    mma_f16(s1[nt], qf1[ks], bf[nt]);
                }
            }

            // ---- ALiBi (exp2 domain), dist shared ----
#pragma unroll
            for (int nt = 0; nt < 8; nt++) {
                float k0f = (float)(kb * 128 + kk * 64 + nt * 8 + 2 * fc);
                float k1f = k0f + 1.f;
                float d0 = fabsf(gq0 - k0f), d1 = fabsf(gq0 - k1f);
                float d2 = fabsf(gq1 - k0f), d3 = fabsf(gq1 - k1f);
                s0[nt][0] = fmaf(-slope0, d0, s0[nt][0]);
                s0[nt][1] = fmaf(-slope0, d1, s0[nt][1]);
                s0[nt][2] = fmaf(-slope0, d2, s0[nt][2]);
                s0[nt][3] = fmaf(-slope0, d3, s0[nt][3]);
                s1[nt][0] = fmaf(-slope1, d0, s1[nt][0]);
                s1[nt][1] = fmaf(-slope1, d1, s1[nt][1]);
                s1[nt][2] = fmaf(-slope1, d2, s1[nt][2]);
                s1[nt][3] = fmaf(-slope1, d3, s1[nt][3]);
            }

            // ---- online softmax head0 ----
            {
                float mt0 = -INFINITY, mt1 = -INFINITY;
#pragma unroll
                for (int nt = 0; nt < 8; nt++) {
                    mt0 = fmaxf(mt0, fmaxf(s0[nt][0], s0[nt][1]));
                    mt1 = fmaxf(mt1, fmaxf(s0[nt][2], s0[nt][3]));
                }
                mt0 = fmaxf(mt0, __shfl_xor_sync(0xffffffffu, mt0, 1));
                mt0 = fmaxf(mt0, __shfl_xor_sync(0xffffffffu, mt0, 2));
                mt1 = fmaxf(mt1, __shfl_xor_sync(0xffffffffu, mt1, 1));
                mt1 = fmaxf(mt1, __shfl_xor_sync(0xffffffffu, mt1, 2));
                float mn0 = fmaxf(m00, mt0), mn1 = fmaxf(m01, mt1);
                float c0 = exp2f(m00 - mn0), c1 = exp2f(m01 - mn1);
                m00 = mn0; m01 = mn1;
#pragma unroll
                for (int nt = 0; nt < 8; nt++) {
                    float p0 = exp2f(s0[nt][0] - mn0);
                    float p1 = exp2f(s0[nt][1] - mn0);
                    float p2 = exp2f(s0[nt][2] - mn1);
                    float p3 = exp2f(s0[nt][3] - mn1);
                    Ps0[r0 * LTT + nt * 4 + fc]       = f2h2(p0, p1);
                    Ps0[(r0 + 8) * LTT + nt * 4 + fc] = f2h2(p2, p3);
                }
#pragma unroll
                for (int nt = 0; nt < 8; nt++) {
                    o0[nt][0] *= c0; o0[nt][1] *= c0;
                    o0[nt][2] *= c1; o0[nt][3] *= c1;
                }
                la0[0] *= c0; la0[1] *= c0; la0[2] *= c1; la0[3] *= c1;
            }
            // ---- online softmax head1 ----
            {
                float mt0 = -INFINITY, mt1 = -INFINITY;
#pragma unroll
                for (int nt = 0; nt < 8; nt++) {
                    mt0 = fmaxf(mt0, fmaxf(s1[nt][0], s1[nt][1]));
                    mt1 = fmaxf(mt1, fmaxf(s1[nt][2], s1[nt][3]));
                }
                mt0 = fmaxf(mt0, __shfl_xor_sync(0xffffffffu, mt0, 1));
                mt0 = fmaxf(mt0, __shfl_xor_sync(0xffffffffu, mt0, 2));
                mt1 = fmaxf(mt1, __shfl_xor_sync(0xffffffffu, mt1, 1));
                mt1 = fmaxf(mt1, __shfl_xor_sync(0xffffffffu, mt1, 2));
                float mn0 = fmaxf(m10, mt0), mn1 = fmaxf(m11, mt1);
                float c0 = exp2f(m10 - mn0), c1 = exp2f(m11 - mn1);
                m10 = mn0; m11 = mn1;
#pragma unroll
                for (int nt = 0; nt < 8; nt++) {
                    float p0 = exp2f(s1[nt][0] - mn0);
                    float p1 = exp2f(s1[nt][1] - mn0);
                    float p2 = exp2f(s1[nt][2] - mn1);
                    float p3 = exp2f(s1[nt][3] - mn1);
                    Ps1[r0 * LTT + nt * 4 + fc]       = f2h2(p0, p1);
                    Ps1[(r0 + 8) * LTT + nt * 4 + fc] = f2h2(p2, p3);
                }
#pragma unroll
                for (int nt = 0; nt < 8; nt++) {
                    o1[nt][0] *= c0; o1[nt][1] *= c0;
                    o1[nt][2] *= c1; o1[nt][3] *= c1;
                }
                la1[0] *= c0; la1[1] *= c0; la1[2] *= c1; la1[3] *= c1;
            }
            __syncwarp();

            // ---- O += P @ V, V fragments shared by both heads ----
#pragma unroll
            for (int ks = 0; ks < 4; ks++) {
                uint32_t af0[4], af1[4], bf[8][2];
                ldsm_x4(af0, ps0u + (((wid * 16 + rowA) * LTT) + ks * 8 + offA) * 4);
                ldsm_x4(af1, ps1u + (((wid * 16 + rowA) * LTT) + ks * 8 + offA) * 4);
#pragma unroll
                for (int ntp = 0; ntp < 4; ntp++) {
                    uint32_t m[4];
                    ldsm_x4(m, vtu + (((ntp * 16 + rowB) * LTV) + kk * 32 + ks * 8 + offB) * 4);
                    bf[ntp * 2][0] = m[0]; bf[ntp * 2][1] = m[1];
                    bf[ntp * 2 + 1][0] = m[2]; bf[ntp * 2 + 1][1] = m[3];
                }
#pragma unroll
                for (int nt = 0; nt < 8; nt++) {
                    mma_f16(o0[nt], af0, bf[nt]);
                    mma_f16(o1[nt], af1, bf[nt]);
                }
                mma_f16(la0, af0, onesb);
                mma_f16(la1, af1, onesb);
            }
            __syncwarp();
        }
    }

    // ---- normalize + write fp16, both heads ----
    {
        float i00 = 1.f / la0[0], i01 = 1.f / la0[2];
        float i10 = 1.f / la1[0], i11 = 1.f / la1[2];
        const int qr = q0 + wid * 16 + fr;
        __half* a0 = g_attn + (size_t)(n * SEQ + qr) * (NH * HD) + h0 * HD;
        __half* a1 = g_attn + (size_t)(n * SEQ + qr + 8) * (NH * HD) + h0 * HD;
#pragma unroll
        for (int nt = 0; nt < 8; nt++) {
            *(uint32_t*)(a0 + nt * 8 + 2 * fc)      = f2h2(o0[nt][0] * i00, o0[nt][1] * i00);
            *(uint32_t*)(a1 + nt * 8 + 2 * fc)      = f2h2(o0[nt][2] * i01, o0[nt][3] * i01);
            *(uint32_t*)(a0 + HD + nt * 8 + 2 * fc) = f2h2(o1[nt][0] * i10, o1[nt][1] * i10);
            *(uint32_t*)(a1 + HD + nt * 8 + 2 * fc) = f2h2(o1[nt][2] * i11, o1[nt][3] * i11);
        }
    }
}

// =====================================================================
// launch
// =====================================================================
extern "C" void kernel_launch(void* const* d_in, const int* in_sizes, int n_in,
                              void* d_out, int out_size)
{
    const float* x  = (const float*)d_in[0];
    const float* Wq = (const float*)d_in[1];
    const float* Wk = (const float*)d_in[2];
    const float* Wv = (const float*)d_in[3];
    const float* Wo = (const float*)d_in[4];
    const float* bo = (const float*)d_in[5];
    float* out = (float*)d_out;

    preround<<<TOT4 / 256, 256>>>(x, Wq, Wk, Wv, Wo);

    cudaFuncSetAttribute(gemm_qkv, cudaFuncAttributeMaxDynamicSharedMemorySize, GSMEM_DYN);
    cudaFuncSetAttribute(gemm_out, cudaFuncAttributeMaxDynamicSharedMemorySize, GSMEM_DYN);

    gemm_qkv<<<dim3(8, MROWS / 128), 256, GSMEM_DYN>>>();

    // flash: one CTA per (q-block, kvh, n), covers 2 heads
    int smemf = (128 * LTK + 64 * LTV + 2 * 128 * LTT) * (int)sizeof(uint32_t);  // 72704
    cudaFuncSetAttribute(flash_mma, cudaFuncAttributeMaxDynamicSharedMemorySize, smemf);
    flash_mma<<<dim3(SEQ / 128, NKV, NB), 256, smemf>>>();

    gemm_out<<<dim3(EMB / 256, MROWS / 128), 256, GSMEM_DYN>>>(bo, out);
}

// round 17
// speedup vs baseline: 1.0831x; 1.0831x over previous
#include <cuda_runtime.h>
#include <cuda_fp16.h>
#include <math.h>
#include <stdint.h>

#define NB   2
#define SEQ  2048
#define EMB  1024
#define NH   16
#define NKV  8
#define HD   64
#define MROWS (NB*SEQ)   // 4096

// ---------------- scratch (no allocations allowed) ----------------
__device__ __half g_q [(size_t)MROWS * NH * HD];   // QSC-scaled fp16
__device__ __half g_k [(size_t)MROWS * NKV * HD];  // fp16
__device__ __half g_vt[(size_t)MROWS * NKV * HD];  // fp16 transposed [nb][kvh][d][s]
__device__ __half g_attn[(size_t)MROWS * NH * HD];
__device__ __half g_xt[(size_t)MROWS * EMB];
__device__ __half g_wq[(size_t)NH * HD * EMB];
__device__ __half g_wk[(size_t)NKV * HD * EMB];
__device__ __half g_wv[(size_t)NKV * HD * EMB];
__device__ __half g_wo[(size_t)EMB * NH * HD];

#define QSC 0.18033688011112042f   // 0.125 * log2(e)

// =====================================================================
// helpers
// =====================================================================
__device__ __forceinline__ uint32_t f2h2(float lo, float hi) {
    uint32_t r;
    asm("cvt.rn.f16x2.f32 %0, %1, %2;" : "=r"(r) : "f"(hi), "f"(lo));
    return r;
}
__device__ __forceinline__ void mma_f16(float* d, const uint32_t* a, const uint32_t* b) {
    asm volatile(
        "mma.sync.aligned.m16n8k16.row.col.f32.f16.f16.f32 "
        "{%0,%1,%2,%3}, {%4,%5,%6,%7}, {%8,%9}, {%0,%1,%2,%3};"
        : "+f"(d[0]), "+f"(d[1]), "+f"(d[2]), "+f"(d[3])
        : "r"(a[0]), "r"(a[1]), "r"(a[2]), "r"(a[3]), "r"(b[0]), "r"(b[1]));
}
__device__ __forceinline__ void ldsm_x4(uint32_t* r, uint32_t addr) {
    asm volatile("ldmatrix.sync.aligned.m8n8.x4.shared.b16 {%0,%1,%2,%3}, [%4];"
        : "=r"(r[0]), "=r"(r[1]), "=r"(r[2]), "=r"(r[3]) : "r"(addr));
}
__device__ __forceinline__ uint32_t smem_u32(const void* p) {
    uint32_t a;
    asm("{ .reg .u64 t; cvta.to.shared.u64 t, %1; cvt.u32.u64 %0, t; }" : "=r"(a) : "l"(p));
    return a;
}
#define CPCA16(dst, src) \
    asm volatile("cp.async.ca.shared.global [%0], [%1], 16;" :: "r"(dst), "l"(src))
#define CP_COMMIT() asm volatile("cp.async.commit_group;" ::: "memory")
#define CP_WAIT(n)  asm volatile("cp.async.wait_group %0;" :: "n"(n) : "memory")

// =====================================================================
// pre-round: x + weights -> fp16 scratch
// =====================================================================
#define X4  (MROWS * EMB / 4)
#define WQ4 (NH * HD * EMB / 4)
#define WK4 (NKV * HD * EMB / 4)
#define TOT4 (X4 + WQ4 + 2 * WK4 + WQ4)

__global__ __launch_bounds__(256)
void preround(const float* __restrict__ x,
              const float* __restrict__ wq, const float* __restrict__ wk,
              const float* __restrict__ wv, const float* __restrict__ wo)
{
    long i = (long)blockIdx.x * 256 + threadIdx.x;
    const float* src; __half* dst; long base;
    if (i < X4)                       { src = x;  dst = g_xt; base = 0; }
    else if (i < X4 + WQ4)            { src = wq; dst = g_wq; base = X4; }
    else if (i < X4 + WQ4 + WK4)      { src = wk; dst = g_wk; base = X4 + WQ4; }
    else if (i < X4 + WQ4 + 2 * WK4)  { src = wv; dst = g_wv; base = X4 + WQ4 + WK4; }
    else                              { src = wo; dst = g_wo; base = X4 + WQ4 + 2 * WK4; }
    long j = (i - base) * 4;
    float4 a = *(const float4*)(src + j);
    uint2 t = { f2h2(a.x, a.y), f2h2(a.z, a.w) };
    *(uint2*)(dst + j) = t;
}

// =====================================================================
// fp16 GEMM (ldmatrix fragments): 256 thr, 8 warps (2x4), warp 64x64,
// CTA 128x256, K-chunk 64 halves, cp.async.ca double-buffered.
// =====================================================================
#define LT 36
#define ABUF (128 * LT)
#define BBUF (256 * LT)
#define TBUF (ABUF + BBUF)
#define GSMEM_DYN (2 * TBUF * 4)

__device__ __forceinline__
void gemm_stage(uint32_t sbase, int buf, const __half* __restrict__ A,
                const __half* __restrict__ B, int K, int m0, int n0, int k0, int tid)
{
    uint32_t dA = sbase + (buf * TBUF) * 4;
    uint32_t dB = dA + ABUF * 4;
#pragma unroll
    for (int p = 0; p < 4; p++) {
        int c = tid + p * 256;
        int row = c >> 3;
        int ch  = c & 7;
        CPCA16(dA + (row * LT + ch * 4) * 4, A + (size_t)(m0 + row) * K + k0 + ch * 8);
    }
#pragma unroll
    for (int p = 0; p < 8; p++) {
        int c = tid + p * 256;
        int row = c >> 3;
        int ch  = c & 7;
        CPCA16(dB + (row * LT + ch * 4) * 4, B + (size_t)(n0 + row) * K + k0 + ch * 8);
    }
    CP_COMMIT();
}

__device__ __forceinline__
void gemm_body(const __half* __restrict__ A, const __half* __restrict__ B,
               const float* __restrict__ bias, void* __restrict__ Cout,
               int N, int K, int m0, int n0, int mode)
{
    extern __shared__ uint32_t gsm[];
    const uint32_t sbase = smem_u32(gsm);

    const int tid  = threadIdx.x;
    const int lane = tid & 31;
    const int wid  = tid >> 5;
    const int wm   = wid >> 2;
    const int wn   = wid & 3;
    const int fr   = lane >> 2;
    const int fc   = lane & 3;

    const int rowA = (lane & 7) + ((lane >> 3) & 1) * 8;
    const int offA = (lane >> 4) * 4;
    const int rowB = (lane & 7) + (lane >> 4) * 8;
    const int offB = ((lane >> 3) & 1) * 4;

    float acc[4][8][4];
#pragma unroll
    for (int mt = 0; mt < 4; mt++)
#pragma unroll
        for (int nt = 0; nt < 8; nt++)
#pragma unroll
            for (int i = 0; i < 4; i++) acc[mt][nt][i] = 0.f;

    gemm_stage(sbase, 0, A, B, K, m0, n0, 0, tid);

    const int NC = K / 64;
    for (int ch = 0; ch < NC; ch++) {
        if (ch + 1 < NC) {
            gemm_stage(sbase, (ch + 1) & 1, A, B, K, m0, n0, (ch + 1) * 64, tid);
            CP_WAIT(1);
        } else {
            CP_WAIT(0);
        }
        __syncthreads();

        const uint32_t asu = sbase + ((ch & 1) * TBUF) * 4;
        const uint32_t bsu = asu + ABUF * 4;

#pragma unroll
        for (int ks = 0; ks < 4; ks++) {
            uint32_t af[4][4], bf[8][2];
#pragma unroll
            for (int mt = 0; mt < 4; mt++)
                ldsm_x4(af[mt], asu + (((wm * 64 + mt * 16 + rowA) * LT) + ks * 8 + offA) * 4);
#pragma unroll
            for (int ntp = 0; ntp < 4; ntp++) {
                uint32_t m[4];
                ldsm_x4(m, bsu + (((wn * 64 + ntp * 16 + rowB) * LT) + ks * 8 + offB) * 4);
                bf[ntp * 2][0] = m[0]; bf[ntp * 2][1] = m[1];
                bf[ntp * 2 + 1][0] = m[2]; bf[ntp * 2 + 1][1] = m[3];
            }
#pragma unroll
            for (int mt = 0; mt < 4; mt++)
#pragma unroll
                for (int nt = 0; nt < 8; nt++)
                    mma_f16(acc[mt][nt], af[mt], bf[nt]);
        }
        __syncthreads();
    }

    const int c2 = fc * 2;
#pragma unroll
    for (int mt = 0; mt < 4; mt++) {
        int m = m0 + wm * 64 + mt * 16 + fr;
#pragma unroll
        for (int nt = 0; nt < 8; nt++) {
            int n = n0 + wn * 64 + nt * 8 + c2;
            if (mode == 0) {
                float* C = (float*)Cout;
                float b0 = bias ? bias[n] : 0.f, b1 = bias ? bias[n + 1] : 0.f;
                float2 v0 = { acc[mt][nt][0] + b0, acc[mt][nt][1] + b1 };
                float2 v1 = { acc[mt][nt][2] + b0, acc[mt][nt][3] + b1 };
                *(float2*)(C + (size_t)m * N + n)       = v0;
                *(float2*)(C + (size_t)(m + 8) * N + n) = v1;
            } else if (mode == 3) {
                int kvh = n >> 6, d = n & 63;
                int nb = m >> 11, s = m & (SEQ - 1);
                size_t rb = ((size_t)(nb * NKV + kvh) * HD + d) * SEQ;
                g_vt[rb + s]           = __float2half(acc[mt][nt][0]);
                g_vt[rb + SEQ + s]     = __float2half(acc[mt][nt][1]);
                g_vt[rb + s + 8]       = __float2half(acc[mt][nt][2]);
                g_vt[rb + SEQ + s + 8] = __float2half(acc[mt][nt][3]);
            } else {
                __half* C = (__half*)Cout;
                float sc = (mode == 2) ? QSC : 1.f;
                *(uint32_t*)(C + (size_t)m * N + n) =
                    f2h2(acc[mt][nt][0] * sc, acc[mt][nt][1] * sc);
                *(uint32_t*)(C + (size_t)(m + 8) * N + n) =
                    f2h2(acc[mt][nt][2] * sc, acc[mt][nt][3] * sc);
            }
        }
    }
}

__global__ __launch_bounds__(256)
void gemm_qkv()
{
    const int bx = blockIdx.x;
    const int m0 = blockIdx.y * 128;
    if (bx < 4)      gemm_body(g_xt, g_wq, nullptr, g_q, NH * HD,  EMB, m0, bx * 256, 2);
    else if (bx < 6) gemm_body(g_xt, g_wk, nullptr, g_k, NKV * HD, EMB, m0, (bx - 4) * 256, 1);
    else             gemm_body(g_xt, g_wv, nullptr, nullptr, NKV * HD, EMB, m0, (bx - 6) * 256, 3);
}

__global__ __launch_bounds__(256)
void gemm_out(const float* __restrict__ bias, float* __restrict__ C)
{
    gemm_body(g_attn, g_wo, bias, C, EMB, EMB, blockIdx.y * 128, blockIdx.x * 256, 0);
}

// =====================================================================
// Flash attention v11 = R14 shape (4 warps x 32 q-rows, BQ=128) +
// cp.async.ca double-buffered K/V staging + ones-mma for l.
// Ks[2]: [128][36]  Vt[2]: [64][68]  Ps: [128][36]
// =====================================================================
#define LTK 36
#define LTV 68
#define LTT 36
#define KVW (128 * LTK + 64 * LTV)      // words per KV buffer: 8960
#define NTI (SEQ / 128)                 // 16 tiles

__global__ __launch_bounds__(128, 2)
void flash_mma()
{
    extern __shared__ uint32_t smf[];
    // layout: KV buf0 [Ks|Vt], KV buf1 [Ks|Vt], Ps
    uint32_t* Ps = smf + 2 * KVW;
    const uint32_t kv0 = smem_u32(smf);
    const uint32_t psu = smem_u32(Ps);

    const int tid  = threadIdx.x;
    const int lane = tid & 31;
    const int wid  = tid >> 5;
    const int fr   = lane >> 2;
    const int fc   = lane & 3;

    const int rowA = (lane & 7) + ((lane >> 3) & 1) * 8;
    const int offA = (lane >> 4) * 4;
    const int rowB = (lane & 7) + (lane >> 4) * 8;
    const int offB = ((lane >> 3) & 1) * 4;

    const int q0 = blockIdx.x * 128;
    const int h  = blockIdx.y;
    const int n  = blockIdx.z;
    const int kvh = h >> 1;
    const float slope2 = exp2f(-(float)(h + 1)) * QSC;

    const uint32_t onesb[2] = { 0x3C003C00u, 0x3C003C00u };

    const __half* kbase  = g_k  + (size_t)(n * SEQ) * (NKV * HD) + kvh * HD;
    const __half* vtbase = g_vt + (size_t)(n * NKV + kvh) * HD * SEQ;

    // ---- stage Q (plain LDG+STS, once) ----
#pragma unroll
    for (int p = 0; p < 8; p++) {
        int u = tid + p * 128;
        int qi = u >> 3;
        int c  = u & 7;
        uint4 t = *(const uint4*)(g_q + (size_t)(n * SEQ + q0 + qi) * (NH * HD)
                                      + h * HD + c * 8);
        *(uint4*)&Ps[qi * LTT + c * 4] = t;
    }

    // ---- cp.async stage KV tile 0 into buf 0 ----
    {
        uint32_t ku = kv0;
        uint32_t vu = kv0 + 128 * LTK * 4;
#pragma unroll
        for (int p = 0; p < 8; p++) {
            int u = tid + p * 128;
            int ki = u >> 3;
            int c  = u & 7;
            CPCA16(ku + (ki * LTK + c * 4) * 4, kbase + (size_t)ki * (NKV * HD) + c * 8);
        }
#pragma unroll
        for (int p = 0; p < 8; p++) {
            int u = tid + p * 128;
            int d = u >> 4;
            int c = u & 15;
            CPCA16(vu + (d * LTV + c * 4) * 4, vtbase + (size_t)d * SEQ + c * 8);
        }
        CP_COMMIT();
    }
    __syncthreads();   // Q visible

    const int r0 = wid * 32 + fr;
    uint32_t qf0[4][4], qf1[4][4];
#pragma unroll
    for (int ks = 0; ks < 4; ks++) {
        ldsm_x4(qf0[ks], psu + (((wid * 32 + rowA) * LTT) + ks * 8 + offA) * 4);
        ldsm_x4(qf1[ks], psu + (((wid * 32 + 16 + rowA) * LTT) + ks * 8 + offA) * 4);
    }

    float o0[8][4], o1[8][4], la0[4], la1[4];
#pragma unroll
    for (int nt = 0; nt < 8; nt++)
#pragma unroll
        for (int i = 0; i < 4; i++) { o0[nt][i] = 0.f; o1[nt][i] = 0.f; }
#pragma unroll
    for (int i = 0; i < 4; i++) { la0[i] = 0.f; la1[i] = 0.f; }
    float m00 = -INFINITY, m01 = -INFINITY, m10 = -INFINITY, m11 = -INFINITY;

    const float gq0 = (float)(q0 + wid * 32 + fr);

    for (int kb = 0; kb < NTI; kb++) {
        const int buf = kb & 1;

        // prefetch next KV tile (WAR-safe: end-sync of iter kb-1 covers buf^1)
        if (kb + 1 < NTI) {
            uint32_t ku = kv0 + ((buf ^ 1) * KVW) * 4;
            uint32_t vu = ku + 128 * LTK * 4;
            const __half* kb2 = kbase + (size_t)((kb + 1) * 128) * (NKV * HD);
            const __half* vb2 = vtbase + (kb + 1) * 128;
#pragma unroll
            for (int p = 0; p < 8; p++) {
                int u = tid + p * 128;
                int ki = u >> 3;
                int c  = u & 7;
                CPCA16(ku + (ki * LTK + c * 4) * 4, kb2 + (size_t)ki * (NKV * HD) + c * 8);
            }
#pragma unroll
            for (int p = 0; p < 8; p++) {
                int u = tid + p * 128;
                int d = u >> 4;
                int c = u & 15;
                CPCA16(vu + (d * LTV + c * 4) * 4, vb2 + (size_t)d * SEQ + c * 8);
            }
            CP_COMMIT();
            CP_WAIT(1);
        } else {
            CP_WAIT(0);
        }
        __syncthreads();   // tile kb visible

        const uint32_t ksu = kv0 + (buf * KVW) * 4;
        const uint32_t vtu = ksu + 128 * LTK * 4;

#pragma unroll
        for (int kk = 0; kk < 2; kk++) {
            float s0[8][4], s1[8][4];
#pragma unroll
            for (int nt = 0; nt < 8; nt++)
#pragma unroll
                for (int i = 0; i < 4; i++) { s0[nt][i] = 0.f; s1[nt][i] = 0.f; }

            // ---- S = Q @ K^T ----
#pragma unroll
            for (int ks = 0; ks < 4; ks++) {
                uint32_t bf[8][2];
#pragma unroll
                for (int ntp = 0; ntp < 4; ntp++) {
                    uint32_t m[4];
                    ldsm_x4(m, ksu + (((kk * 64 + ntp * 16 + rowB) * LTK) + ks * 8 + offB) * 4);
                    bf[ntp * 2][0] = m[0]; bf[ntp * 2][1] = m[1];
                    bf[ntp * 2 + 1][0] = m[2]; bf[ntp * 2 + 1][1] = m[3];
                }
#pragma unroll
                for (int nt = 0; nt < 8; nt++) {
                    mma_f16(s0[nt], qf0[ks], bf[nt]);
                    mma_f16(s1[nt], qf1[ks], bf[nt]);
                }
            }

            // ---- ALiBi (exp2 domain) ----
#pragma unroll
            for (int nt = 0; nt < 8; nt++) {
                float k0f = (float)(kb * 128 + kk * 64 + nt * 8 + 2 * fc);
                float k1f = k0f + 1.f;
                s0[nt][0] = fmaf(-slope2, fabsf(gq0 - k0f), s0[nt][0]);
                s0[nt][1] = fmaf(-slope2, fabsf(gq0 - k1f), s0[nt][1]);
                s0[nt][2] = fmaf(-slope2, fabsf((gq0 + 8.f) - k0f), s0[nt][2]);
                s0[nt][3] = fmaf(-slope2, fabsf((gq0 + 8.f) - k1f), s0[nt][3]);
                s1[nt][0] = fmaf(-slope2, fabsf((gq0 + 16.f) - k0f), s1[nt][0]);
                s1[nt][1] = fmaf(-slope2, fabsf((gq0 + 16.f) - k1f), s1[nt][1]);
                s1[nt][2] = fmaf(-slope2, fabsf((gq0 + 24.f) - k0f), s1[nt][2]);
                s1[nt][3] = fmaf(-slope2, fabsf((gq0 + 24.f) - k1f), s1[nt][3]);
            }

            // ---- online softmax block0 (rows r0, r0+8) ----
            {
                float mt0 = -INFINITY, mt1 = -INFINITY;
#pragma unroll
                for (int nt = 0; nt < 8; nt++) {
                    mt0 = fmaxf(mt0, fmaxf(s0[nt][0], s0[nt][1]));
                    mt1 = fmaxf(mt1, fmaxf(s0[nt][2], s0[nt][3]));
                }
                mt0 = fmaxf(mt0, __shfl_xor_sync(0xffffffffu, mt0, 1));
                mt0 = fmaxf(mt0, __shfl_xor_sync(0xffffffffu, mt0, 2));
                mt1 = fmaxf(mt1, __shfl_xor_sync(0xffffffffu, mt1, 1));
                mt1 = fmaxf(mt1, __shfl_xor_sync(0xffffffffu, mt1, 2));
                float mn0 = fmaxf(m00, mt0), mn1 = fmaxf(m01, mt1);
                float c0 = exp2f(m00 - mn0), c1 = exp2f(m01 - mn1);
                m00 = mn0; m01 = mn1;
#pragma unroll
                for (int nt = 0; nt < 8; nt++) {
                    float p0 = exp2f(s0[nt][0] - mn0);
                    float p1 = exp2f(s0[nt][1] - mn0);
                    float p2 = exp2f(s0[nt][2] - mn1);
                    float p3 = exp2f(s0[nt][3] - mn1);
                    Ps[r0 * LTT + nt * 4 + fc]       = f2h2(p0, p1);
                    Ps[(r0 + 8) * LTT + nt * 4 + fc] = f2h2(p2, p3);
                }
#pragma unroll
                for (int nt = 0; nt < 8; nt++) {
                    o0[nt][0] *= c0; o0[nt][1] *= c0;
                    o0[nt][2] *= c1; o0[nt][3] *= c1;
                }
                la0[0] *= c0; la0[1] *= c0; la0[2] *= c1; la0[3] *= c1;
            }
            // ---- online softmax block1 (rows r0+16, r0+24) ----
            {
                float mt0 = -INFINITY, mt1 = -INFINITY;
#pragma unroll
                for (int nt = 0; nt < 8; nt++) {
                    mt0 = fmaxf(mt0, fmaxf(s1[nt][0], s1[nt][1]));
                    mt1 = fmaxf(mt1, fmaxf(s1[nt][2], s1[nt][3]));
                }
                mt0 = fmaxf(mt0, __shfl_xor_sync(0xffffffffu, mt0, 1));
                mt0 = fmaxf(mt0, __shfl_xor_sync(0xffffffffu, mt0, 2));
                mt1 = fmaxf(mt1, __shfl_xor_sync(0xffffffffu, mt1, 1));
                mt1 = fmaxf(mt1, __shfl_xor_sync(0xffffffffu, mt1, 2));
                float mn0 = fmaxf(m10, mt0), mn1 = fmaxf(m11, mt1);
                float c0 = exp2f(m10 - mn0), c1 = exp2f(m11 - mn1);
                m10 = mn0; m11 = mn1;
#pragma unroll
                for (int nt = 0; nt < 8; nt++) {
                    float p0 = exp2f(s1[nt][0] - mn0);
                    float p1 = exp2f(s1[nt][1] - mn0);
                    float p2 = exp2f(s1[nt][2] - mn1);
                    float p3 = exp2f(s1[nt][3] - mn1);
                    Ps[(r0 + 16) * LTT + nt * 4 + fc] = f2h2(p0, p1);
                    Ps[(r0 + 24) * LTT + nt * 4 + fc] = f2h2(p2, p3);
                }
#pragma unroll
                for (int nt = 0; nt < 8; nt++) {
                    o1[nt][0] *= c0; o1[nt][1] *= c0;
                    o1[nt][2] *= c1; o1[nt][3] *= c1;
                }
                la1[0] *= c0; la1[1] *= c0; la1[2] *= c1; la1[3] *= c1;
            }
            __syncwarp();

            // ---- O += P @ V ; l += P @ ones ----
#pragma unroll
            for (int ks = 0; ks < 4; ks++) {
                uint32_t af0[4], af1[4], bf[8][2];
                ldsm_x4(af0, psu + (((wid * 32 + rowA) * LTT) + ks * 8 + offA) * 4);
                ldsm_x4(af1, psu + (((wid * 32 + 16 + rowA) * LTT) + ks * 8 + offA) * 4);
#pragma unroll
                for (int ntp = 0; ntp < 4; ntp++) {
                    uint32_t m[4];
                    ldsm_x4(m, vtu + (((ntp * 16 + rowB) * LTV) + kk * 32 + ks * 8 + offB) * 4);
                    bf[ntp * 2][0] = m[0]; bf[ntp * 2][1] = m[1];
                    bf[ntp * 2 + 1][0] = m[2]; bf[ntp * 2 + 1][1] = m[3];
                }
#pragma unroll
                for (int nt = 0; nt < 8; nt++) {
                    mma_f16(o0[nt], af0, bf[nt]);
                    mma_f16(o1[nt], af1, bf[nt]);
                }
                mma_f16(la0, af0, onesb);
                mma_f16(la1, af1, onesb);
            }
            __syncwarp();
        }
        __syncthreads();   // all warps done reading buf before iter kb+1 overwrites buf^1 / kb+2 overwrites buf
    }

    // ---- normalize + write fp16 ----
    {
        float i00 = 1.f / la0[0], i01 = 1.f / la0[2];
        float i10 = 1.f / la1[0], i11 = 1.f / la1[2];
        const int qr = q0 + wid * 32 + fr;
        __half* b0 = g_attn + (size_t)(n * SEQ + qr) * (NH * HD) + h * HD;
        __half* b1 = g_attn + (size_t)(n * SEQ + qr + 8) * (NH * HD) + h * HD;
        __half* b2 = g_attn + (size_t)(n * SEQ + qr + 16) * (NH * HD) + h * HD;
        __half* b3 = g_attn + (size_t)(n * SEQ + qr + 24) * (NH * HD) + h * HD;
#pragma unroll
        for (int nt = 0; nt < 8; nt++) {
            *(uint32_t*)(b0 + nt * 8 + 2 * fc) = f2h2(o0[nt][0] * i00, o0[nt][1] * i00);
            *(uint32_t*)(b1 + nt * 8 + 2 * fc) = f2h2(o0[nt][2] * i01, o0[nt][3] * i01);
            *(uint32_t*)(b2 + nt * 8 + 2 * fc) = f2h2(o1[nt][0] * i10, o1[nt][1] * i10);
            *(uint32_t*)(b3 + nt * 8 + 2 * fc) = f2h2(o1[nt][2] * i11, o1[nt][3] * i11);
        }
    }
}

// =====================================================================
// launch
// =====================================================================
extern "C" void kernel_launch(void* const* d_in, const int* in_sizes, int n_in,
                              void* d_out, int out_size)
{
    const float* x  = (const float*)d_in[0];
    const float* Wq = (const float*)d_in[1];
    const float* Wk = (const float*)d_in[2];
    const float* Wv = (const float*)d_in[3];
    const float* Wo = (const float*)d_in[4];
    const float* bo = (const float*)d_in[5];
    float* out = (float*)d_out;

    preround<<<TOT4 / 256, 256>>>(x, Wq, Wk, Wv, Wo);

    cudaFuncSetAttribute(gemm_qkv, cudaFuncAttributeMaxDynamicSharedMemorySize, GSMEM_DYN);
    cudaFuncSetAttribute(gemm_out, cudaFuncAttributeMaxDynamicSharedMemorySize, GSMEM_DYN);

    gemm_qkv<<<dim3(8, MROWS / 128), 256, GSMEM_DYN>>>();

    int smemf = (2 * KVW + 128 * LTT) * (int)sizeof(uint32_t);   // 90112
    cudaFuncSetAttribute(flash_mma, cudaFuncAttributeMaxDynamicSharedMemorySize, smemf);
    flash_mma<<<dim3(SEQ / 128, NH, NB), 128, smemf>>>();

    gemm_out<<<dim3(EMB / 256, MROWS / 128), 256, GSMEM_DYN>>>(bo, out);
}